// round 13
// baseline (speedup 1.0000x reference)
#include <cuda_runtime.h>
#include <cstdint>

// Problem constants
#define T_TOK  8192
#define DDIM   1024
#define HDIM   2048
#define NEXP   8
#define TOPK   2
#define ROWS_TOT 24576       // T*K routed rows + T shared rows
#define MAXTILES 200

// ---------------- scratch (fp16 stored as raw bits) --------------------------
__device__ unsigned short g_Ah[(size_t)T_TOK * DDIM];                  // h in fp16
__device__ unsigned g_W1h[(size_t)(NEXP + 1) * HDIM * DDIM / 2];       // expert 8 = shared
__device__ unsigned g_W3h[(size_t)(NEXP + 1) * HDIM * DDIM / 2];
__device__ unsigned g_W2h[(size_t)(NEXP + 1) * DDIM * HDIM / 2];
__device__ unsigned g_U[(size_t)ROWS_TOT * HDIM / 2];                  // U = silu(h1)*h3, fp16x2
__device__ int      g_rows [ROWS_TOT];
__device__ float    g_wslot[T_TOK * 3];
__device__ int      g_tok_e[T_TOK * TOPK];
__device__ int      g_cnt [16];
__device__ int      g_off [16];
__device__ int      g_tile_e[MAXTILES + 8];
__device__ int      g_tile_m[MAXTILES + 8];
__device__ int      g_ntiles;

// ---------------- helpers ----------------------------------------------------
__device__ __forceinline__ uint32_t smem_u32(const void* p) {
    uint32_t a;
    asm("{ .reg .u64 t; cvta.to.shared.u64 t, %1; cvt.u32.u64 %0, t; }" : "=r"(a) : "l"(p));
    return a;
}
__device__ __forceinline__ unsigned f2h2(float lo, float hi) {
    unsigned r;
    asm("cvt.rn.f16x2.f32 %0, %1, %2;" : "=r"(r) : "f"(hi), "f"(lo));
    return r;
}
__device__ __forceinline__ void mma_fp16(float* c, const unsigned* a, const unsigned* b) {
    asm volatile(
        "mma.sync.aligned.m16n8k16.row.col.f32.f16.f16.f32 "
        "{%0,%1,%2,%3}, {%4,%5,%6,%7}, {%8,%9}, {%0,%1,%2,%3};\n"
        : "+f"(c[0]), "+f"(c[1]), "+f"(c[2]), "+f"(c[3])
        : "r"(a[0]), "r"(a[1]), "r"(a[2]), "r"(a[3]), "r"(b[0]), "r"(b[1]));
}
__device__ __forceinline__ void ldsm4(unsigned* r, uint32_t addr) {
    asm volatile("ldmatrix.sync.aligned.m8n8.x4.shared.b16 {%0,%1,%2,%3}, [%4];"
        : "=r"(r[0]), "=r"(r[1]), "=r"(r[2]), "=r"(r[3]) : "r"(addr));
}
__device__ __forceinline__ float silu(float x) { return x / (1.f + __expf(-x)); }
__device__ __forceinline__ void red_v2(float* p, float a, float b) {
    asm volatile("red.global.add.v2.f32 [%0], {%1, %2};" :: "l"(p), "f"(a), "f"(b) : "memory");
}

#define CPA16(sm, gm) asm volatile("cp.async.cg.shared.global [%0], [%1], 16;" :: "r"(sm), "l"(gm))
#define CPCOMMIT()    asm volatile("cp.async.commit_group;" ::: "memory")
#define CPWAIT2()     asm volatile("cp.async.wait_group 2;" ::: "memory")

// ---------------- small kernels ----------------------------------------------
__global__ void zero_kernel() {
    if (threadIdx.x < 16) g_cnt[threadIdx.x] = 0;
}

// ---------------- fused prep: weight cvt + gate + out-zero -------------------
#define NBW  (NEXP * HDIM * DDIM / 4)
#define NSW  (HDIM * DDIM / 4)
#define NSEG (NBW + NSW)
#define NTOTW (3 * NSEG)
#define PREP_THREADS 256
#define CVT_UNROLL   4
#define CVT_BLOCKS   (NTOTW / (PREP_THREADS * CVT_UNROLL))   // 13824
#define GATE_BLOCKS  (T_TOK / 8)
#define ZO_UNROLL    4
#define ZO_BLOCKS    (T_TOK * DDIM / 4 / (PREP_THREADS * ZO_UNROLL))  // 2048
#define PREP_BLOCKS  (CVT_BLOCKS + GATE_BLOCKS + ZO_BLOCKS)

__global__ __launch_bounds__(PREP_THREADS) void prep_kernel(
    const float4* __restrict__ W1, const float4* __restrict__ sw1,
    const float4* __restrict__ W3, const float4* __restrict__ sw3,
    const float4* __restrict__ W2, const float4* __restrict__ sw2,
    const float* __restrict__ hf, const float* __restrict__ Wg,
    float4* __restrict__ outz)
{
    const int blk = blockIdx.x;
    if (blk < CVT_BLOCKS) {
        const int stride = CVT_BLOCKS * PREP_THREADS;
        int i0 = blk * PREP_THREADS + threadIdx.x;
        const float4* src[CVT_UNROLL];
        uint2*       dst[CVT_UNROLL];
#pragma unroll
        for (int u = 0; u < CVT_UNROLL; u++) {
            int i = i0 + u * stride;
            int q = i / NSEG;
            int r = i - q * NSEG;
            const float4* big = (q == 0) ? W1 : (q == 1) ? W3 : W2;
            const float4* sh  = (q == 0) ? sw1 : (q == 1) ? sw3 : sw2;
            uint2* d = (q == 0) ? (uint2*)g_W1h : (q == 1) ? (uint2*)g_W3h : (uint2*)g_W2h;
            src[u] = (r < NBW) ? (big + r) : (sh + (r - NBW));
            dst[u] = d + r;
        }
        float4 v[CVT_UNROLL];
#pragma unroll
        for (int u = 0; u < CVT_UNROLL; u++) v[u] = *src[u];
#pragma unroll
        for (int u = 0; u < CVT_UNROLL; u++)
            *dst[u] = make_uint2(f2h2(v[u].x, v[u].y), f2h2(v[u].z, v[u].w));
        return;
    }
    if (blk < CVT_BLOCKS + ZO_BLOCKS) {
        int zb = blk - CVT_BLOCKS;
        int i0 = zb * PREP_THREADS + threadIdx.x;
        const int stride = ZO_BLOCKS * PREP_THREADS;
        float4 z = make_float4(0.f, 0.f, 0.f, 0.f);
#pragma unroll
        for (int u = 0; u < ZO_UNROLL; u++) outz[i0 + u * stride] = z;
        return;
    }
    // ---- gate + h->fp16 convert (one warp per token) ----
    int gb = blk - CVT_BLOCKS - ZO_BLOCKS;
    int t    = gb * 8 + (threadIdx.x >> 5);
    int lane = threadIdx.x & 31;

    float s[NEXP];
#pragma unroll
    for (int e = 0; e < NEXP; e++) s[e] = 0.f;
    const float* x = hf + (size_t)t * DDIM;
    for (int d = lane; d < DDIM; d += 32) {
        float xv = x[d];
        unsigned short hb;
        asm("cvt.rn.f16.f32 %0, %1;" : "=h"(hb) : "f"(xv));
        g_Ah[(size_t)t * DDIM + d] = hb;
#pragma unroll
        for (int e = 0; e < NEXP; e++) s[e] += xv * Wg[e * DDIM + d];
    }
#pragma unroll
    for (int e = 0; e < NEXP; e++) {
#pragma unroll
        for (int o = 16; o; o >>= 1) s[e] += __shfl_xor_sync(0xffffffffu, s[e], o);
    }
    if (lane == 0) {
        float m = s[0];
#pragma unroll
        for (int e = 1; e < NEXP; e++) m = fmaxf(m, s[e]);
        float p[NEXP];
#pragma unroll
        for (int e = 0; e < NEXP; e++) p[e] = __expf(s[e] - m);
        float v0 = -1.f, v1 = -1.f; int i0 = 0, i1 = 0;
#pragma unroll
        for (int e = 0; e < NEXP; e++) {
            if (p[e] > v0)      { v1 = v0; i1 = i0; v0 = p[e]; i0 = e; }
            else if (p[e] > v1) { v1 = p[e]; i1 = e; }
        }
        float inv = 1.f / (v0 + v1);
        g_tok_e[t * 2 + 0] = i0;
        g_tok_e[t * 2 + 1] = i1;
        g_wslot[t * 3 + 0] = v0 * inv;
        g_wslot[t * 3 + 1] = v1 * inv;
        g_wslot[t * 3 + 2] = 1.f;
        atomicAdd(&g_cnt[i0], 1);
        atomicAdd(&g_cnt[i1], 1);
        g_rows[T_TOK * TOPK + t] = t * 4 + 2;
    }
}

// ---------------- merged setup + scatter (single block) ----------------------
__global__ __launch_bounds__(1024) void setup_scatter_kernel() {
    __shared__ int s_off[16];
    __shared__ int s_fill[16];
    if (threadIdx.x == 0) {
        g_off[0] = 0;
        for (int e = 0; e < NEXP; e++) g_off[e + 1] = g_off[e] + g_cnt[e];
        g_off[NEXP + 1] = g_off[NEXP] + T_TOK;
        int nt = 0;
        for (int e = 0; e <= NEXP; e++) {
            int Me = g_off[e + 1] - g_off[e];
            for (int j = 0; j < Me; j += 128) { g_tile_e[nt] = e; g_tile_m[nt] = j; nt++; }
        }
        g_ntiles = nt;
    }
    if (threadIdx.x < 16) { s_fill[threadIdx.x] = 0; }
    __syncthreads();
    if (threadIdx.x < 16) s_off[threadIdx.x] = g_off[threadIdx.x];
    __syncthreads();
    for (int i = threadIdx.x; i < T_TOK * TOPK; i += 1024) {
        int e = g_tok_e[i];
        int pos = atomicAdd(&s_fill[e], 1);
        g_rows[s_off[e] + pos] = (i >> 1) * 4 + (i & 1);
    }
}

// ---------------- fused GEMM1: U = silu(A@W1^T) * (A@W3^T) -------------------
// 128m x 128h tile, BK=32, 512 threads, 6-slot cp.async ring,
// one __syncthreads per 2 k-stages (wait -> barrier -> issue -> compute).
#define A1STG  (128 * 80)
#define B1STG  (256 * 80)
#define STG1   (A1STG + B1STG)              // 30720
#define SMEM1_BYTES (6 * STG1)              // 184320

__global__ __launch_bounds__(512, 1) void gemm1_fused() {
    const int tileIdx = blockIdx.y;
    if (tileIdx >= g_ntiles) return;
    const int e   = g_tile_e[tileIdx];
    const int m0  = g_tile_m[tileIdx];
    const int off = g_off[e];
    const int Me  = g_off[e + 1] - off;
    const int n0  = blockIdx.x * 128;
    const size_t wst = (size_t)HDIM * DDIM / 2;

    extern __shared__ unsigned char smem[];
    const uint32_t smb = smem_u32(smem);
    const int tid  = threadIdx.x;
    const int wid  = tid >> 5, lane = tid & 31;

    // ---- loader: 3 x 16B chunks / thread / stage ----
    const char* gsrc[3];
    uint32_t    sdst[3];
#pragma unroll
    for (int j = 0; j < 3; j++) {
        int id = tid + j * 512;
        if (id < 512) {
            int row = id >> 2, kc = id & 3;
            int ml = m0 + row;
            int gi = off + (ml < Me ? ml : 0);
            int tok = g_rows[gi] >> 2;
            gsrc[j] = (const char*)g_Ah + ((size_t)tok * DDIM + kc * 8) * 2;
            sdst[j] = (uint32_t)(row * 80 + kc * 16);
        } else {
            int bid = id - 512;
            int row = bid >> 2, kc = bid & 3;      // 0..255
            const unsigned* W = (row < 128)
                ? (g_W1h + (size_t)e * wst + (size_t)(n0 + row) * (DDIM / 2))
                : (g_W3h + (size_t)e * wst + (size_t)(n0 + row - 128) * (DDIM / 2));
            gsrc[j] = (const char*)W + kc * 16;
            sdst[j] = (uint32_t)(A1STG + row * 80 + kc * 16);
        }
    }

#define G1_ISSUE(S, pf) do {                                                \
        uint32_t _b = smb + (S) * STG1;                                     \
        size_t _go = (size_t)(pf) * 64;                                     \
        _Pragma("unroll")                                                   \
        for (int j = 0; j < 3; j++) CPA16(_b + sdst[j], gsrc[j] + _go);     \
    } while (0)

    const int mb = (wid & 3) * 32, nb = (wid >> 2) * 32;
    const uint32_t afl = (lane & 15) * 80 + (lane >> 4) * 16;
    const int gid = lane >> 2, tig = lane & 3;

    float acc1[2][4][4], acc3[2][4][4];
#pragma unroll
    for (int mi = 0; mi < 2; mi++)
#pragma unroll
        for (int ni = 0; ni < 4; ni++)
#pragma unroll
            for (int q = 0; q < 4; q++) { acc1[mi][ni][q] = 0.f; acc3[mi][ni][q] = 0.f; }

#define G1_COMP(S) do {                                                            \
        const uint32_t Ab = smb + (S) * STG1;                                      \
        const uint32_t Bb = Ab + A1STG;                                            \
        _Pragma("unroll")                                                          \
        for (int kc = 0; kc < 2; kc++) {                                           \
            unsigned af[2][4];                                                     \
            _Pragma("unroll")                                                      \
            for (int mi = 0; mi < 2; mi++)                                         \
                ldsm4(af[mi], Ab + (mb + mi * 16) * 80 + afl + kc * 32);           \
            unsigned b1f[2][4], b3f[2][4];                                         \
            _Pragma("unroll")                                                      \
            for (int p = 0; p < 2; p++) {                                          \
                ldsm4(b1f[p], Bb + (nb + p * 16) * 80 + afl + kc * 32);            \
                ldsm4(b3f[p], Bb + (128 + nb + p * 16) * 80 + afl + kc * 32);      \
            }                                                                      \
            _Pragma("unroll")                                                      \
            for (int mi = 0; mi < 2; mi++)                                         \
                _Pragma("unroll")                                                  \
                for (int ni = 0; ni < 4; ni++) {                                   \
                    const int p = ni >> 1, s = ni & 1;                             \
                    unsigned bb1[2] = { b1f[p][s], b1f[p][s + 2] };                \
                    unsigned bb3[2] = { b3f[p][s], b3f[p][s + 2] };                \
                    mma_fp16(acc1[mi][ni], af[mi], bb1);                           \
                    mma_fp16(acc3[mi][ni], af[mi], bb3);                           \
                }                                                                  \
        }                                                                          \
    } while (0)

// pair: wait (tiles kte,kte+1 retired) -> barrier (publish) -> prefetch -> compute
#define G1_PAIR(s0, s1, w0, w1, kte, KTmax) do {                            \
        CPWAIT2();                                                          \
        __syncthreads();                                                    \
        if ((kte) + 4 < (KTmax)) G1_ISSUE(w0, (kte) + 4);                   \
        CPCOMMIT();                                                         \
        if ((kte) + 5 < (KTmax)) G1_ISSUE(w1, (kte) + 5);                   \
        CPCOMMIT();                                                         \
        G1_COMP(s0);                                                        \
        G1_COMP(s1);                                                        \
    } while (0)

    // prologue: tiles 0..3 -> slots 0..3 (4 groups in flight)
    G1_ISSUE(0, 0); CPCOMMIT();
    G1_ISSUE(1, 1); CPCOMMIT();
    G1_ISSUE(2, 2); CPCOMMIT();
    G1_ISSUE(3, 3); CPCOMMIT();

    const int KT = DDIM / 32;    // 32
    for (int kte = 0; kte < KT; kte += 6) {
        G1_PAIR(0, 1, 4, 5, kte, KT);
        if (kte + 2 < KT) G1_PAIR(2, 3, 0, 1, kte + 2, KT);
        if (kte + 4 < KT) G1_PAIR(4, 5, 2, 3, kte + 4, KT);
    }
#undef G1_PAIR
#undef G1_ISSUE
#undef G1_COMP

    // epilogue: u = silu(h1)*h3 as fp16x2
#pragma unroll
    for (int mi = 0; mi < 2; mi++) {
#pragma unroll
        for (int half = 0; half < 2; half++) {
            int ml = m0 + mb + mi * 16 + gid + half * 8;
            if (ml < Me) {
                int gi = off + ml;
                unsigned* up = g_U + (size_t)gi * (HDIM / 2);
#pragma unroll
                for (int ni = 0; ni < 4; ni++) {
                    int n = n0 + nb + ni * 8 + tig * 2;
                    float vx = silu(acc1[mi][ni][half * 2 + 0]) * acc3[mi][ni][half * 2 + 0];
                    float vy = silu(acc1[mi][ni][half * 2 + 1]) * acc3[mi][ni][half * 2 + 1];
                    up[n >> 1] = f2h2(vx, vy);
                }
            }
        }
    }
}

// ---------------- GEMM2: out[token] += w * (U @ W2^T)  (v2 RED accumulate) ---
// 128m x 128n tile, BK=32, 512 threads (16 warps of 32m x 32n), 8-slot ring,
// one __syncthreads per 2 k-stages.
#define A2STG  (128 * 80)
#define B2STG  (128 * 80)
#define STG2   (A2STG + B2STG)              // 20480
#define SMEM2_BYTES (8 * STG2)              // 163840

__global__ __launch_bounds__(512, 1) void gemm2(float* __restrict__ out) {
    const int tileIdx = blockIdx.y;
    if (tileIdx >= g_ntiles) return;
    const int e   = g_tile_e[tileIdx];
    const int m0  = g_tile_m[tileIdx];
    const int off = g_off[e];
    const int Me  = g_off[e + 1] - off;
    const int n0  = blockIdx.x * 128;
    const size_t wst = (size_t)DDIM * HDIM / 2;

    extern __shared__ unsigned char smem[];
    const uint32_t smb = smem_u32(smem);
    const int tid = threadIdx.x;
    const int wid = tid >> 5, lane = tid & 31;

    // ---- loader: 2 x 16B chunks / thread / stage ----
    const char* gsrc[2];
    uint32_t    sdst[2];
#pragma unroll
    for (int j = 0; j < 2; j++) {
        int id = tid + j * 512;
        if (id < 512) {
            int row = id >> 2, kc = id & 3;
            int ml = m0 + row;
            int gi = off + (ml < Me ? ml : 0);
            gsrc[j] = (const char*)g_U + ((size_t)gi * HDIM + kc * 8) * 2;
            sdst[j] = (uint32_t)(row * 80 + kc * 16);
        } else {
            int bid = id - 512;
            int row = bid >> 2, kc = bid & 3;
            gsrc[j] = (const char*)(g_W2h + (size_t)e * wst
                                    + (size_t)(n0 + row) * (HDIM / 2)) + kc * 16;
            sdst[j] = (uint32_t)(A2STG + row * 80 + kc * 16);
        }
    }

#define G2_ISSUE(S, pf) do {                                                \
        uint32_t _b = smb + (S) * STG2;                                     \
        size_t _go = (size_t)(pf) * 64;                                     \
        _Pragma("unroll")                                                   \
        for (int j = 0; j < 2; j++) CPA16(_b + sdst[j], gsrc[j] + _go);     \
    } while (0)

    const int mb = (wid & 3) * 32, nb = (wid >> 2) * 32;
    const uint32_t afl = (lane & 15) * 80 + (lane >> 4) * 16;
    const int gid = lane >> 2, tig = lane & 3;

    float acc[2][4][4];
#pragma unroll
    for (int mi = 0; mi < 2; mi++)
#pragma unroll
        for (int ni = 0; ni < 4; ni++)
#pragma unroll
            for (int q = 0; q < 4; q++) acc[mi][ni][q] = 0.f;

#define G2_COMP(S) do {                                                            \
        const uint32_t Ab = smb + (S) * STG2;                                      \
        const uint32_t Bb = Ab + A2STG;                                            \
        _Pragma("unroll")                                                          \
        for (int kc = 0; kc < 2; kc++) {                                           \
            unsigned af[2][4];                                                     \
            _Pragma("unroll")                                                      \
            for (int mi = 0; mi < 2; mi++)                                         \
                ldsm4(af[mi], Ab + (mb + mi * 16) * 80 + afl + kc * 32);           \
            unsigned bf[2][4];                                                     \
            _Pragma("unroll")                                                      \
            for (int p = 0; p < 2; p++)                                            \
                ldsm4(bf[p], Bb + (nb + p * 16) * 80 + afl + kc * 32);             \
            _Pragma("unroll")                                                      \
            for (int mi = 0; mi < 2; mi++)                                         \
                _Pragma("unroll")                                                  \
                for (int ni = 0; ni < 4; ni++) {                                   \
                    const int p = ni >> 1, s = ni & 1;                             \
                    unsigned bb[2] = { bf[p][s], bf[p][s + 2] };                   \
                    mma_fp16(acc[mi][ni], af[mi], bb);                             \
                }                                                                  \
        }                                                                          \
    } while (0)

#define G2_PAIR(s0, s1, w0, w1, kte, KTmax) do {                            \
        CPWAIT2();                                                          \
        __syncthreads();                                                    \
        if ((kte) + 4 < (KTmax)) G2_ISSUE(w0, (kte) + 4);                   \
        CPCOMMIT();                                                         \
        if ((kte) + 5 < (KTmax)) G2_ISSUE(w1, (kte) + 5);                   \
        CPCOMMIT();                                                         \
        G2_COMP(s0);                                                        \
        G2_COMP(s1);                                                        \
    } while (0)

    // prologue: tiles 0..3 -> slots 0..3
    G2_ISSUE(0, 0); CPCOMMIT();
    G2_ISSUE(1, 1); CPCOMMIT();
    G2_ISSUE(2, 2); CPCOMMIT();
    G2_ISSUE(3, 3); CPCOMMIT();

    const int KT = HDIM / 32;    // 64, divisible by 8
    for (int kte = 0; kte < KT; kte += 8) {
        G2_PAIR(0, 1, 4, 5, kte,     KT);
        G2_PAIR(2, 3, 6, 7, kte + 2, KT);
        G2_PAIR(4, 5, 0, 1, kte + 4, KT);
        G2_PAIR(6, 7, 2, 3, kte + 6, KT);
    }
#undef G2_PAIR
#undef G2_ISSUE
#undef G2_COMP

    // epilogue: scale + vector-RED accumulate into output token rows
#pragma unroll
    for (int mi = 0; mi < 2; mi++) {
#pragma unroll
        for (int half = 0; half < 2; half++) {
            int ml = m0 + mb + mi * 16 + gid + half * 8;
            if (ml < Me) {
                int gi = off + ml;
                int info = g_rows[gi];
                int tok  = info >> 2;
                int slot = tok * 3 + (info & 3);
                float w = g_wslot[slot];
                float* yp = out + (size_t)tok * DDIM;
#pragma unroll
                for (int ni = 0; ni < 4; ni++) {
                    int n = n0 + nb + ni * 8 + tig * 2;
                    red_v2(yp + n, acc[mi][ni][half * 2 + 0] * w,
                                   acc[mi][ni][half * 2 + 1] * w);
                }
            }
        }
    }
}

// ---------------- launch -----------------------------------------------------
extern "C" void kernel_launch(void* const* d_in, const int* in_sizes, int n_in,
                              void* d_out, int out_size)
{
    const float* h   = (const float*)d_in[0];
    const float* sw1 = (const float*)d_in[1];
    const float* sw2 = (const float*)d_in[2];
    const float* sw3 = (const float*)d_in[3];
    const float* W1  = (const float*)d_in[4];
    const float* W2  = (const float*)d_in[5];
    const float* W3  = (const float*)d_in[6];
    const float* Wg  = (const float*)d_in[7];
    float* out = (float*)d_out;

    static bool attr_done = false;
    if (!attr_done) {
        cudaFuncSetAttribute(gemm1_fused, cudaFuncAttributeMaxDynamicSharedMemorySize, SMEM1_BYTES);
        cudaFuncSetAttribute(gemm2,       cudaFuncAttributeMaxDynamicSharedMemorySize, SMEM2_BYTES);
        attr_done = true;
    }

    zero_kernel<<<1, 32>>>();
    prep_kernel<<<PREP_BLOCKS, PREP_THREADS>>>(
        (const float4*)W1, (const float4*)sw1,
        (const float4*)W3, (const float4*)sw3,
        (const float4*)W2, (const float4*)sw2,
        h, Wg, (float4*)out);
    setup_scatter_kernel<<<1, 1024>>>();

    dim3 grid1(HDIM / 128, MAXTILES);
    gemm1_fused<<<grid1, 512, SMEM1_BYTES>>>();

    dim3 grid2(DDIM / 128, MAXTILES);
    gemm2<<<grid2, 512, SMEM2_BYTES>>>(out);
}

// round 14
// speedup vs baseline: 1.1293x; 1.1293x over previous
#include <cuda_runtime.h>
#include <cstdint>

// Problem constants
#define T_TOK  8192
#define DDIM   1024
#define HDIM   2048
#define NEXP   8
#define TOPK   2
#define ROWS_TOT 24576       // T*K routed rows + T shared rows
#define MAXTILES 200

// ---------------- scratch (fp16 stored as raw bits) --------------------------
__device__ unsigned short g_Ah[(size_t)T_TOK * DDIM];                  // h in fp16
__device__ unsigned g_W1h[(size_t)(NEXP + 1) * HDIM * DDIM / 2];       // expert 8 = shared
__device__ unsigned g_W3h[(size_t)(NEXP + 1) * HDIM * DDIM / 2];
__device__ unsigned g_W2h[(size_t)(NEXP + 1) * DDIM * HDIM / 2];
__device__ unsigned g_U[(size_t)ROWS_TOT * HDIM / 2];                  // U = silu(h1)*h3, fp16x2
__device__ int      g_rows [ROWS_TOT];
__device__ float    g_wslot[T_TOK * 3];
__device__ int      g_tok_e[T_TOK * TOPK];
__device__ int      g_cnt [16];
__device__ int      g_off [16];
__device__ int      g_tile_e[MAXTILES + 8];
__device__ int      g_tile_m[MAXTILES + 8];
__device__ int      g_ntiles;

// ---------------- helpers ----------------------------------------------------
__device__ __forceinline__ uint32_t smem_u32(const void* p) {
    uint32_t a;
    asm("{ .reg .u64 t; cvta.to.shared.u64 t, %1; cvt.u32.u64 %0, t; }" : "=r"(a) : "l"(p));
    return a;
}
__device__ __forceinline__ unsigned f2h2(float lo, float hi) {
    unsigned r;
    asm("cvt.rn.f16x2.f32 %0, %1, %2;" : "=r"(r) : "f"(hi), "f"(lo));
    return r;
}
__device__ __forceinline__ void mma_fp16(float* c, const unsigned* a, const unsigned* b) {
    asm volatile(
        "mma.sync.aligned.m16n8k16.row.col.f32.f16.f16.f32 "
        "{%0,%1,%2,%3}, {%4,%5,%6,%7}, {%8,%9}, {%0,%1,%2,%3};\n"
        : "+f"(c[0]), "+f"(c[1]), "+f"(c[2]), "+f"(c[3])
        : "r"(a[0]), "r"(a[1]), "r"(a[2]), "r"(a[3]), "r"(b[0]), "r"(b[1]));
}
__device__ __forceinline__ void ldsm4(unsigned* r, uint32_t addr) {
    asm volatile("ldmatrix.sync.aligned.m8n8.x4.shared.b16 {%0,%1,%2,%3}, [%4];"
        : "=r"(r[0]), "=r"(r[1]), "=r"(r[2]), "=r"(r[3]) : "r"(addr));
}
__device__ __forceinline__ float silu(float x) { return x / (1.f + __expf(-x)); }
__device__ __forceinline__ void red_v2(float* p, float a, float b) {
    asm volatile("red.global.add.v2.f32 [%0], {%1, %2};" :: "l"(p), "f"(a), "f"(b) : "memory");
}

#define CPA16(sm, gm) asm volatile("cp.async.cg.shared.global [%0], [%1], 16;" :: "r"(sm), "l"(gm))
#define CPCOMMIT()    asm volatile("cp.async.commit_group;" ::: "memory")
#define CPWAIT2()     asm volatile("cp.async.wait_group 2;" ::: "memory")

// ---------------- small kernels ----------------------------------------------
__global__ void zero_kernel() {
    if (threadIdx.x < 16) g_cnt[threadIdx.x] = 0;
}

// ---------------- fused prep: weight cvt + gate + out-zero -------------------
#define NBW  (NEXP * HDIM * DDIM / 4)
#define NSW  (HDIM * DDIM / 4)
#define NSEG (NBW + NSW)
#define NTOTW (3 * NSEG)
#define PREP_THREADS 256
#define CVT_UNROLL   4
#define CVT_BLOCKS   (NTOTW / (PREP_THREADS * CVT_UNROLL))   // 13824
#define GATE_BLOCKS  (T_TOK / 8)
#define ZO_UNROLL    4
#define ZO_BLOCKS    (T_TOK * DDIM / 4 / (PREP_THREADS * ZO_UNROLL))  // 2048
#define PREP_BLOCKS  (CVT_BLOCKS + GATE_BLOCKS + ZO_BLOCKS)

__global__ __launch_bounds__(PREP_THREADS) void prep_kernel(
    const float4* __restrict__ W1, const float4* __restrict__ sw1,
    const float4* __restrict__ W3, const float4* __restrict__ sw3,
    const float4* __restrict__ W2, const float4* __restrict__ sw2,
    const float* __restrict__ hf, const float* __restrict__ Wg,
    float4* __restrict__ outz)
{
    const int blk = blockIdx.x;
    if (blk < CVT_BLOCKS) {
        const int stride = CVT_BLOCKS * PREP_THREADS;
        int i0 = blk * PREP_THREADS + threadIdx.x;
        const float4* src[CVT_UNROLL];
        uint2*       dst[CVT_UNROLL];
#pragma unroll
        for (int u = 0; u < CVT_UNROLL; u++) {
            int i = i0 + u * stride;
            int q = i / NSEG;
            int r = i - q * NSEG;
            const float4* big = (q == 0) ? W1 : (q == 1) ? W3 : W2;
            const float4* sh  = (q == 0) ? sw1 : (q == 1) ? sw3 : sw2;
            uint2* d = (q == 0) ? (uint2*)g_W1h : (q == 1) ? (uint2*)g_W3h : (uint2*)g_W2h;
            src[u] = (r < NBW) ? (big + r) : (sh + (r - NBW));
            dst[u] = d + r;
        }
        float4 v[CVT_UNROLL];
#pragma unroll
        for (int u = 0; u < CVT_UNROLL; u++) v[u] = *src[u];
#pragma unroll
        for (int u = 0; u < CVT_UNROLL; u++)
            *dst[u] = make_uint2(f2h2(v[u].x, v[u].y), f2h2(v[u].z, v[u].w));
        return;
    }
    if (blk < CVT_BLOCKS + ZO_BLOCKS) {
        int zb = blk - CVT_BLOCKS;
        int i0 = zb * PREP_THREADS + threadIdx.x;
        const int stride = ZO_BLOCKS * PREP_THREADS;
        float4 z = make_float4(0.f, 0.f, 0.f, 0.f);
#pragma unroll
        for (int u = 0; u < ZO_UNROLL; u++) outz[i0 + u * stride] = z;
        return;
    }
    // ---- gate + h->fp16 convert (one warp per token) ----
    int gb = blk - CVT_BLOCKS - ZO_BLOCKS;
    int t    = gb * 8 + (threadIdx.x >> 5);
    int lane = threadIdx.x & 31;

    float s[NEXP];
#pragma unroll
    for (int e = 0; e < NEXP; e++) s[e] = 0.f;
    const float* x = hf + (size_t)t * DDIM;
    for (int d = lane; d < DDIM; d += 32) {
        float xv = x[d];
        unsigned short hb;
        asm("cvt.rn.f16.f32 %0, %1;" : "=h"(hb) : "f"(xv));
        g_Ah[(size_t)t * DDIM + d] = hb;
#pragma unroll
        for (int e = 0; e < NEXP; e++) s[e] += xv * Wg[e * DDIM + d];
    }
#pragma unroll
    for (int e = 0; e < NEXP; e++) {
#pragma unroll
        for (int o = 16; o; o >>= 1) s[e] += __shfl_xor_sync(0xffffffffu, s[e], o);
    }
    if (lane == 0) {
        float m = s[0];
#pragma unroll
        for (int e = 1; e < NEXP; e++) m = fmaxf(m, s[e]);
        float p[NEXP];
#pragma unroll
        for (int e = 0; e < NEXP; e++) p[e] = __expf(s[e] - m);
        float v0 = -1.f, v1 = -1.f; int i0 = 0, i1 = 0;
#pragma unroll
        for (int e = 0; e < NEXP; e++) {
            if (p[e] > v0)      { v1 = v0; i1 = i0; v0 = p[e]; i0 = e; }
            else if (p[e] > v1) { v1 = p[e]; i1 = e; }
        }
        float inv = 1.f / (v0 + v1);
        g_tok_e[t * 2 + 0] = i0;
        g_tok_e[t * 2 + 1] = i1;
        g_wslot[t * 3 + 0] = v0 * inv;
        g_wslot[t * 3 + 1] = v1 * inv;
        g_wslot[t * 3 + 2] = 1.f;
        atomicAdd(&g_cnt[i0], 1);
        atomicAdd(&g_cnt[i1], 1);
        g_rows[T_TOK * TOPK + t] = t * 4 + 2;
    }
}

// ---------------- merged setup + scatter (single block) ----------------------
__global__ __launch_bounds__(1024) void setup_scatter_kernel() {
    __shared__ int s_off[16];
    __shared__ int s_fill[16];
    if (threadIdx.x == 0) {
        g_off[0] = 0;
        for (int e = 0; e < NEXP; e++) g_off[e + 1] = g_off[e] + g_cnt[e];
        g_off[NEXP + 1] = g_off[NEXP] + T_TOK;
        int nt = 0;
        for (int e = 0; e <= NEXP; e++) {
            int Me = g_off[e + 1] - g_off[e];
            for (int j = 0; j < Me; j += 128) { g_tile_e[nt] = e; g_tile_m[nt] = j; nt++; }
        }
        g_ntiles = nt;
    }
    if (threadIdx.x < 16) { s_fill[threadIdx.x] = 0; }
    __syncthreads();
    if (threadIdx.x < 16) s_off[threadIdx.x] = g_off[threadIdx.x];
    __syncthreads();
    for (int i = threadIdx.x; i < T_TOK * TOPK; i += 1024) {
        int e = g_tok_e[i];
        int pos = atomicAdd(&s_fill[e], 1);
        g_rows[s_off[e] + pos] = (i >> 1) * 4 + (i & 1);
    }
}

// ---------------- fused GEMM1: U = silu(A@W1^T) * (A@W3^T) -------------------
// 128m x 64h tile, BK=32, 256 threads (8 warps of 32m x 32h x 2 weights),
// 4-stage cp.async ring (per-stage wait->barrier->issue->compute), 2 CTAs/SM.
#define NST    4
#define A1STG  (128 * 80)
#define B1STG  (128 * 80)            // 64 rows W1 + 64 rows W3
#define STG1   (A1STG + B1STG)       // 20480
#define SMEM1_BYTES (NST * STG1)     // 81920 -> 2 CTAs/SM

__global__ __launch_bounds__(256, 2) void gemm1_fused() {
    const int tileIdx = blockIdx.y;
    if (tileIdx >= g_ntiles) return;
    const int e   = g_tile_e[tileIdx];
    const int m0  = g_tile_m[tileIdx];
    const int off = g_off[e];
    const int Me  = g_off[e + 1] - off;
    const int n0  = blockIdx.x * 64;
    const size_t wst = (size_t)HDIM * DDIM / 2;

    extern __shared__ unsigned char smem[];
    const uint32_t smb = smem_u32(smem);
    const int tid  = threadIdx.x;
    const int wid  = tid >> 5, lane = tid & 31;

    // ---- loader: 4 x 16B chunks / thread / stage (1024 chunks) ----
    const char* gsrc[4];
    uint32_t    sdst[4];
#pragma unroll
    for (int j = 0; j < 4; j++) {
        int id = tid + j * 256;
        if (id < 512) {
            int row = id >> 2, kc = id & 3;
            int ml = m0 + row;
            int gi = off + (ml < Me ? ml : 0);
            int tok = g_rows[gi] >> 2;
            gsrc[j] = (const char*)g_Ah + ((size_t)tok * DDIM + kc * 8) * 2;
            sdst[j] = (uint32_t)(row * 80 + kc * 16);
        } else {
            int bid = id - 512;
            int row = bid >> 2, kc = bid & 3;      // 0..127
            const unsigned* W = (row < 64)
                ? (g_W1h + (size_t)e * wst + (size_t)(n0 + row) * (DDIM / 2))
                : (g_W3h + (size_t)e * wst + (size_t)(n0 + row - 64) * (DDIM / 2));
            gsrc[j] = (const char*)W + kc * 16;
            sdst[j] = (uint32_t)(A1STG + row * 80 + kc * 16);
        }
    }

#define G1_ISSUE(S, pf) do {                                                \
        uint32_t _b = smb + (S) * STG1;                                     \
        size_t _go = (size_t)(pf) * 64;                                     \
        _Pragma("unroll")                                                   \
        for (int j = 0; j < 4; j++) CPA16(_b + sdst[j], gsrc[j] + _go);     \
    } while (0)

    const int mb = (wid & 3) * 32, nb = (wid >> 2) * 32;
    const uint32_t afl = (lane & 15) * 80 + (lane >> 4) * 16;
    const int gid = lane >> 2, tig = lane & 3;

    float acc1[2][4][4], acc3[2][4][4];
#pragma unroll
    for (int mi = 0; mi < 2; mi++)
#pragma unroll
        for (int ni = 0; ni < 4; ni++)
#pragma unroll
            for (int q = 0; q < 4; q++) { acc1[mi][ni][q] = 0.f; acc3[mi][ni][q] = 0.f; }

    // prologue: stages 0..2
    G1_ISSUE(0, 0); CPCOMMIT();
    G1_ISSUE(1, 1); CPCOMMIT();
    G1_ISSUE(2, 2); CPCOMMIT();

    const int KT = DDIM / 32;    // 32, multiple of 4
    for (int kt0 = 0; kt0 < KT; kt0 += 4) {
#pragma unroll
        for (int c = 0; c < 4; c++) {
            const int kt = kt0 + c;
            CPWAIT2();
            __syncthreads();
            const int pf = kt + NST - 1;
            if (pf < KT) G1_ISSUE((c + 3) & 3, pf);
            CPCOMMIT();

            const uint32_t Ab = smb + c * STG1;     // constant stage offset
            const uint32_t Bb = Ab + A1STG;
#pragma unroll
            for (int kc = 0; kc < 2; kc++) {
                unsigned af[2][4];
#pragma unroll
                for (int mi = 0; mi < 2; mi++)
                    ldsm4(af[mi], Ab + (mb + mi * 16) * 80 + afl + kc * 32);
                unsigned b1f[2][4], b3f[2][4];
#pragma unroll
                for (int p = 0; p < 2; p++) {
                    ldsm4(b1f[p], Bb + (nb + p * 16) * 80 + afl + kc * 32);
                    ldsm4(b3f[p], Bb + (64 + nb + p * 16) * 80 + afl + kc * 32);
                }
#pragma unroll
                for (int mi = 0; mi < 2; mi++)
#pragma unroll
                    for (int ni = 0; ni < 4; ni++) {
                        const int p = ni >> 1, s = ni & 1;
                        unsigned bb1[2] = { b1f[p][s], b1f[p][s + 2] };
                        unsigned bb3[2] = { b3f[p][s], b3f[p][s + 2] };
                        mma_fp16(acc1[mi][ni], af[mi], bb1);
                        mma_fp16(acc3[mi][ni], af[mi], bb3);
                    }
            }
        }
    }
#undef G1_ISSUE

    // epilogue: u = silu(h1)*h3 as fp16x2
#pragma unroll
    for (int mi = 0; mi < 2; mi++) {
#pragma unroll
        for (int half = 0; half < 2; half++) {
            int ml = m0 + mb + mi * 16 + gid + half * 8;
            if (ml < Me) {
                int gi = off + ml;
                unsigned* up = g_U + (size_t)gi * (HDIM / 2);
#pragma unroll
                for (int ni = 0; ni < 4; ni++) {
                    int n = n0 + nb + ni * 8 + tig * 2;
                    float vx = silu(acc1[mi][ni][half * 2 + 0]) * acc3[mi][ni][half * 2 + 0];
                    float vy = silu(acc1[mi][ni][half * 2 + 1]) * acc3[mi][ni][half * 2 + 1];
                    up[n >> 1] = f2h2(vx, vy);
                }
            }
        }
    }
}

// ---------------- GEMM2: out[token] += w * (U @ W2^T)  (v2 RED accumulate) ---
// 128m x 128n tile, BK=32, 256 threads (8 warps of 64m x 32n), 4-stage cp.async.
// R11-proven configuration.
#define A2STG  (128 * 80)
#define B2STG  (128 * 80)
#define STG2   (A2STG + B2STG)
#define SMEM2_BYTES (NST * STG2)     // 81920

__global__ __launch_bounds__(256, 1) void gemm2(float* __restrict__ out) {
    const int tileIdx = blockIdx.y;
    if (tileIdx >= g_ntiles) return;
    const int e   = g_tile_e[tileIdx];
    const int m0  = g_tile_m[tileIdx];
    const int off = g_off[e];
    const int Me  = g_off[e + 1] - off;
    const int n0  = blockIdx.x * 128;
    const size_t wst = (size_t)DDIM * HDIM / 2;

    extern __shared__ unsigned char smem[];
    const uint32_t smb = smem_u32(smem);
    const int tid = threadIdx.x;
    const int wid = tid >> 5, lane = tid & 31;

    const char* gsrc[4];
    uint32_t    sdst[4];
#pragma unroll
    for (int j = 0; j < 4; j++) {
        int id = tid + j * 256;
        if (id < 512) {
            int row = id >> 2, kc = id & 3;
            int ml = m0 + row;
            int gi = off + (ml < Me ? ml : 0);
            gsrc[j] = (const char*)g_U + ((size_t)gi * HDIM + kc * 8) * 2;
            sdst[j] = (uint32_t)(row * 80 + kc * 16);
        } else {
            int bid = id - 512;
            int row = bid >> 2, kc = bid & 3;
            gsrc[j] = (const char*)(g_W2h + (size_t)e * wst
                                    + (size_t)(n0 + row) * (HDIM / 2)) + kc * 16;
            sdst[j] = (uint32_t)(A2STG + row * 80 + kc * 16);
        }
    }

#define G2_ISSUE(S, pf) do {                                                \
        uint32_t _b = smb + (S) * STG2;                                     \
        size_t _go = (size_t)(pf) * 64;                                     \
        _Pragma("unroll")                                                   \
        for (int j = 0; j < 4; j++) CPA16(_b + sdst[j], gsrc[j] + _go);     \
    } while (0)

    const int mb = (wid & 1) * 64, nb = (wid >> 1) * 32;
    const uint32_t afl = (lane & 15) * 80 + (lane >> 4) * 16;
    const int gid = lane >> 2, tig = lane & 3;

    float acc[4][4][4];
#pragma unroll
    for (int mi = 0; mi < 4; mi++)
#pragma unroll
        for (int ni = 0; ni < 4; ni++)
#pragma unroll
            for (int q = 0; q < 4; q++) acc[mi][ni][q] = 0.f;

    G2_ISSUE(0, 0); CPCOMMIT();
    G2_ISSUE(1, 1); CPCOMMIT();
    G2_ISSUE(2, 2); CPCOMMIT();

    const int KT = HDIM / 32;    // 64, multiple of 4
    for (int kt0 = 0; kt0 < KT; kt0 += 4) {
#pragma unroll
        for (int c = 0; c < 4; c++) {
            const int kt = kt0 + c;
            CPWAIT2();
            __syncthreads();
            const int pf = kt + NST - 1;
            if (pf < KT) G2_ISSUE((c + 3) & 3, pf);
            CPCOMMIT();

            const uint32_t Ab = smb + c * STG2;
            const uint32_t Bb = Ab + A2STG;
#pragma unroll
            for (int kc = 0; kc < 2; kc++) {
                unsigned af[4][4];
#pragma unroll
                for (int mi = 0; mi < 4; mi++)
                    ldsm4(af[mi], Ab + (mb + mi * 16) * 80 + afl + kc * 32);
                unsigned bf[2][4];
#pragma unroll
                for (int p = 0; p < 2; p++)
                    ldsm4(bf[p], Bb + (nb + p * 16) * 80 + afl + kc * 32);
#pragma unroll
                for (int mi = 0; mi < 4; mi++)
#pragma unroll
                    for (int ni = 0; ni < 4; ni++) {
                        const int p = ni >> 1, s = ni & 1;
                        unsigned bb[2] = { bf[p][s], bf[p][s + 2] };
                        mma_fp16(acc[mi][ni], af[mi], bb);
                    }
            }
        }
    }
#undef G2_ISSUE

    // epilogue: scale + vector-RED accumulate into output token rows
#pragma unroll
    for (int mi = 0; mi < 4; mi++) {
#pragma unroll
        for (int half = 0; half < 2; half++) {
            int ml = m0 + mb + mi * 16 + gid + half * 8;
            if (ml < Me) {
                int gi = off + ml;
                int info = g_rows[gi];
                int tok  = info >> 2;
                int slot = tok * 3 + (info & 3);
                float w = g_wslot[slot];
                float* yp = out + (size_t)tok * DDIM;
#pragma unroll
                for (int ni = 0; ni < 4; ni++) {
                    int n = n0 + nb + ni * 8 + tig * 2;
                    red_v2(yp + n, acc[mi][ni][half * 2 + 0] * w,
                                   acc[mi][ni][half * 2 + 1] * w);
                }
            }
        }
    }
}

// ---------------- launch -----------------------------------------------------
extern "C" void kernel_launch(void* const* d_in, const int* in_sizes, int n_in,
                              void* d_out, int out_size)
{
    const float* h   = (const float*)d_in[0];
    const float* sw1 = (const float*)d_in[1];
    const float* sw2 = (const float*)d_in[2];
    const float* sw3 = (const float*)d_in[3];
    const float* W1  = (const float*)d_in[4];
    const float* W2  = (const float*)d_in[5];
    const float* W3  = (const float*)d_in[6];
    const float* Wg  = (const float*)d_in[7];
    float* out = (float*)d_out;

    static bool attr_done = false;
    if (!attr_done) {
        cudaFuncSetAttribute(gemm1_fused, cudaFuncAttributeMaxDynamicSharedMemorySize, SMEM1_BYTES);
        cudaFuncSetAttribute(gemm2,       cudaFuncAttributeMaxDynamicSharedMemorySize, SMEM2_BYTES);
        attr_done = true;
    }

    zero_kernel<<<1, 32>>>();
    prep_kernel<<<PREP_BLOCKS, PREP_THREADS>>>(
        (const float4*)W1, (const float4*)sw1,
        (const float4*)W3, (const float4*)sw3,
        (const float4*)W2, (const float4*)sw2,
        h, Wg, (float4*)out);
    setup_scatter_kernel<<<1, 1024>>>();

    dim3 grid1(HDIM / 64, MAXTILES);     // 32 n-tiles of 64 h-cols
    gemm1_fused<<<grid1, 256, SMEM1_BYTES>>>();

    dim3 grid2(DDIM / 128, MAXTILES);
    gemm2<<<grid2, 256, SMEM2_BYTES>>>(out);
}

// round 17
// speedup vs baseline: 1.1299x; 1.0006x over previous
#include <cuda_runtime.h>
#include <cstdint>

// Problem constants
#define T_TOK  8192
#define DDIM   1024
#define HDIM   2048
#define NEXP   8
#define TOPK   2
#define ROWS_TOT 24576       // T*K routed rows + T shared rows
#define MAXTILES 200

// ---------------- scratch (fp16 stored as raw bits) --------------------------
__device__ unsigned short g_Ah[(size_t)T_TOK * DDIM];                  // h in fp16
__device__ unsigned g_W1h[(size_t)(NEXP + 1) * HDIM * DDIM / 2];       // expert 8 = shared
__device__ unsigned g_W3h[(size_t)(NEXP + 1) * HDIM * DDIM / 2];
__device__ unsigned g_W2h[(size_t)(NEXP + 1) * DDIM * HDIM / 2];
__device__ unsigned g_U[(size_t)ROWS_TOT * HDIM / 2];                  // U = silu(h1)*h3, fp16x2
__device__ int      g_rows [ROWS_TOT];
__device__ float    g_wslot[T_TOK * 3];
__device__ int      g_tok_e[T_TOK * TOPK];
__device__ int      g_cnt [16];
__device__ int      g_off [16];
__device__ int      g_tile_e[MAXTILES + 8];
__device__ int      g_tile_m[MAXTILES + 8];
__device__ int      g_ntiles;

// ---------------- helpers ----------------------------------------------------
__device__ __forceinline__ uint32_t smem_u32(const void* p) {
    uint32_t a;
    asm("{ .reg .u64 t; cvta.to.shared.u64 t, %1; cvt.u32.u64 %0, t; }" : "=r"(a) : "l"(p));
    return a;
}
__device__ __forceinline__ unsigned f2h2(float lo, float hi) {
    unsigned r;
    asm("cvt.rn.f16x2.f32 %0, %1, %2;" : "=r"(r) : "f"(hi), "f"(lo));
    return r;
}
__device__ __forceinline__ void mma_fp16(float* c, const unsigned* a, const unsigned* b) {
    asm volatile(
        "mma.sync.aligned.m16n8k16.row.col.f32.f16.f16.f32 "
        "{%0,%1,%2,%3}, {%4,%5,%6,%7}, {%8,%9}, {%0,%1,%2,%3};\n"
        : "+f"(c[0]), "+f"(c[1]), "+f"(c[2]), "+f"(c[3])
        : "r"(a[0]), "r"(a[1]), "r"(a[2]), "r"(a[3]), "r"(b[0]), "r"(b[1]));
}
__device__ __forceinline__ void ldsm4(unsigned* r, uint32_t addr) {
    asm volatile("ldmatrix.sync.aligned.m8n8.x4.shared.b16 {%0,%1,%2,%3}, [%4];"
        : "=r"(r[0]), "=r"(r[1]), "=r"(r[2]), "=r"(r[3]) : "r"(addr));
}
__device__ __forceinline__ float silu(float x) { return x / (1.f + __expf(-x)); }
__device__ __forceinline__ void red_v2(float* p, float a, float b) {
    asm volatile("red.global.add.v2.f32 [%0], {%1, %2};" :: "l"(p), "f"(a), "f"(b) : "memory");
}

#define CPA16(sm, gm) asm volatile("cp.async.cg.shared.global [%0], [%1], 16;" :: "r"(sm), "l"(gm))
#define CPCOMMIT()    asm volatile("cp.async.commit_group;" ::: "memory")
#define CPWAIT2()     asm volatile("cp.async.wait_group 2;" ::: "memory")

// ---------------- small kernels ----------------------------------------------
__global__ void zero_kernel() {
    if (threadIdx.x < 16) g_cnt[threadIdx.x] = 0;
}

// ---------------- fused prep: weight cvt + gate + out-zero -------------------
#define NBW  (NEXP * HDIM * DDIM / 4)
#define NSW  (HDIM * DDIM / 4)
#define NSEG (NBW + NSW)
#define NTOTW (3 * NSEG)
#define PREP_THREADS 256
#define CVT_UNROLL   4
#define CVT_BLOCKS   (NTOTW / (PREP_THREADS * CVT_UNROLL))   // 13824
#define GATE_BLOCKS  (T_TOK / 8)
#define ZO_UNROLL    4
#define ZO_BLOCKS    (T_TOK * DDIM / 4 / (PREP_THREADS * ZO_UNROLL))  // 2048
#define PREP_BLOCKS  (CVT_BLOCKS + GATE_BLOCKS + ZO_BLOCKS)

__global__ __launch_bounds__(PREP_THREADS) void prep_kernel(
    const float4* __restrict__ W1, const float4* __restrict__ sw1,
    const float4* __restrict__ W3, const float4* __restrict__ sw3,
    const float4* __restrict__ W2, const float4* __restrict__ sw2,
    const float* __restrict__ hf, const float* __restrict__ Wg,
    float4* __restrict__ outz)
{
    const int blk = blockIdx.x;
    if (blk < CVT_BLOCKS) {
        const int stride = CVT_BLOCKS * PREP_THREADS;
        int i0 = blk * PREP_THREADS + threadIdx.x;
        const float4* src[CVT_UNROLL];
        uint2*       dst[CVT_UNROLL];
#pragma unroll
        for (int u = 0; u < CVT_UNROLL; u++) {
            int i = i0 + u * stride;
            int q = i / NSEG;
            int r = i - q * NSEG;
            const float4* big = (q == 0) ? W1 : (q == 1) ? W3 : W2;
            const float4* sh  = (q == 0) ? sw1 : (q == 1) ? sw3 : sw2;
            uint2* d = (q == 0) ? (uint2*)g_W1h : (q == 1) ? (uint2*)g_W3h : (uint2*)g_W2h;
            src[u] = (r < NBW) ? (big + r) : (sh + (r - NBW));
            dst[u] = d + r;
        }
        float4 v[CVT_UNROLL];
#pragma unroll
        for (int u = 0; u < CVT_UNROLL; u++) v[u] = *src[u];
#pragma unroll
        for (int u = 0; u < CVT_UNROLL; u++)
            *dst[u] = make_uint2(f2h2(v[u].x, v[u].y), f2h2(v[u].z, v[u].w));
        return;
    }
    if (blk < CVT_BLOCKS + ZO_BLOCKS) {
        int zb = blk - CVT_BLOCKS;
        int i0 = zb * PREP_THREADS + threadIdx.x;
        const int stride = ZO_BLOCKS * PREP_THREADS;
        float4 z = make_float4(0.f, 0.f, 0.f, 0.f);
#pragma unroll
        for (int u = 0; u < ZO_UNROLL; u++) outz[i0 + u * stride] = z;
        return;
    }
    // ---- gate + h->fp16 convert (one warp per token) ----
    int gb = blk - CVT_BLOCKS - ZO_BLOCKS;
    int t    = gb * 8 + (threadIdx.x >> 5);
    int lane = threadIdx.x & 31;

    float s[NEXP];
#pragma unroll
    for (int e = 0; e < NEXP; e++) s[e] = 0.f;
    const float* x = hf + (size_t)t * DDIM;
    for (int d = lane; d < DDIM; d += 32) {
        float xv = x[d];
        unsigned short hb;
        asm("cvt.rn.f16.f32 %0, %1;" : "=h"(hb) : "f"(xv));
        g_Ah[(size_t)t * DDIM + d] = hb;
#pragma unroll
        for (int e = 0; e < NEXP; e++) s[e] += xv * Wg[e * DDIM + d];
    }
#pragma unroll
    for (int e = 0; e < NEXP; e++) {
#pragma unroll
        for (int o = 16; o; o >>= 1) s[e] += __shfl_xor_sync(0xffffffffu, s[e], o);
    }
    if (lane == 0) {
        float m = s[0];
#pragma unroll
        for (int e = 1; e < NEXP; e++) m = fmaxf(m, s[e]);
        float p[NEXP];
#pragma unroll
        for (int e = 0; e < NEXP; e++) p[e] = __expf(s[e] - m);
        float v0 = -1.f, v1 = -1.f; int i0 = 0, i1 = 0;
#pragma unroll
        for (int e = 0; e < NEXP; e++) {
            if (p[e] > v0)      { v1 = v0; i1 = i0; v0 = p[e]; i0 = e; }
            else if (p[e] > v1) { v1 = p[e]; i1 = e; }
        }
        float inv = 1.f / (v0 + v1);
        g_tok_e[t * 2 + 0] = i0;
        g_tok_e[t * 2 + 1] = i1;
        g_wslot[t * 3 + 0] = v0 * inv;
        g_wslot[t * 3 + 1] = v1 * inv;
        g_wslot[t * 3 + 2] = 1.f;
        atomicAdd(&g_cnt[i0], 1);
        atomicAdd(&g_cnt[i1], 1);
        g_rows[T_TOK * TOPK + t] = t * 4 + 2;
    }
}

// ---------------- merged setup + scatter (single block) ----------------------
__global__ __launch_bounds__(1024) void setup_scatter_kernel() {
    __shared__ int s_off[16];
    __shared__ int s_fill[16];
    if (threadIdx.x == 0) {
        g_off[0] = 0;
        for (int e = 0; e < NEXP; e++) g_off[e + 1] = g_off[e] + g_cnt[e];
        g_off[NEXP + 1] = g_off[NEXP] + T_TOK;
        int nt = 0;
        for (int e = 0; e <= NEXP; e++) {
            int Me = g_off[e + 1] - g_off[e];
            for (int j = 0; j < Me; j += 128) { g_tile_e[nt] = e; g_tile_m[nt] = j; nt++; }
        }
        g_ntiles = nt;
    }
    if (threadIdx.x < 16) { s_fill[threadIdx.x] = 0; }
    __syncthreads();
    if (threadIdx.x < 16) s_off[threadIdx.x] = g_off[threadIdx.x];
    __syncthreads();
    for (int i = threadIdx.x; i < T_TOK * TOPK; i += 1024) {
        int e = g_tok_e[i];
        int pos = atomicAdd(&s_fill[e], 1);
        g_rows[s_off[e] + pos] = (i >> 1) * 4 + (i & 1);
    }
}

// ---------------- fused GEMM1: U = silu(A@W1^T) * (A@W3^T) -------------------
// 128m x 64h tile, BK=32, 256 threads (8 warps of 32m x 32h x 2 weights),
// 4-stage cp.async ring (per-stage wait->barrier->issue->compute), 2 CTAs/SM.
#define NST    4
#define A1STG  (128 * 80)
#define B1STG  (128 * 80)            // 64 rows W1 + 64 rows W3
#define STG1   (A1STG + B1STG)       // 20480
#define SMEM1_BYTES (NST * STG1)     // 81920 -> 2 CTAs/SM

__global__ __launch_bounds__(256, 2) void gemm1_fused() {
    const int tileIdx = blockIdx.y;
    if (tileIdx >= g_ntiles) return;
    const int e   = g_tile_e[tileIdx];
    const int m0  = g_tile_m[tileIdx];
    const int off = g_off[e];
    const int Me  = g_off[e + 1] - off;
    const int n0  = blockIdx.x * 64;
    const size_t wst = (size_t)HDIM * DDIM / 2;

    extern __shared__ unsigned char smem[];
    const uint32_t smb = smem_u32(smem);
    const int tid  = threadIdx.x;
    const int wid  = tid >> 5, lane = tid & 31;

    // ---- loader: 4 x 16B chunks / thread / stage (1024 chunks) ----
    const char* gsrc[4];
    uint32_t    sdst[4];
#pragma unroll
    for (int j = 0; j < 4; j++) {
        int id = tid + j * 256;
        if (id < 512) {
            int row = id >> 2, kc = id & 3;
            int ml = m0 + row;
            int gi = off + (ml < Me ? ml : 0);
            int tok = g_rows[gi] >> 2;
            gsrc[j] = (const char*)g_Ah + ((size_t)tok * DDIM + kc * 8) * 2;
            sdst[j] = (uint32_t)(row * 80 + kc * 16);
        } else {
            int bid = id - 512;
            int row = bid >> 2, kc = bid & 3;      // 0..127
            const unsigned* W = (row < 64)
                ? (g_W1h + (size_t)e * wst + (size_t)(n0 + row) * (DDIM / 2))
                : (g_W3h + (size_t)e * wst + (size_t)(n0 + row - 64) * (DDIM / 2));
            gsrc[j] = (const char*)W + kc * 16;
            sdst[j] = (uint32_t)(A1STG + row * 80 + kc * 16);
        }
    }

#define G1_ISSUE(S, pf) do {                                                \
        uint32_t _b = smb + (S) * STG1;                                     \
        size_t _go = (size_t)(pf) * 64;                                     \
        _Pragma("unroll")                                                   \
        for (int j = 0; j < 4; j++) CPA16(_b + sdst[j], gsrc[j] + _go);     \
    } while (0)

    const int mb = (wid & 3) * 32, nb = (wid >> 2) * 32;
    const uint32_t afl = (lane & 15) * 80 + (lane >> 4) * 16;
    const int gid = lane >> 2, tig = lane & 3;

    float acc1[2][4][4], acc3[2][4][4];
#pragma unroll
    for (int mi = 0; mi < 2; mi++)
#pragma unroll
        for (int ni = 0; ni < 4; ni++)
#pragma unroll
            for (int q = 0; q < 4; q++) { acc1[mi][ni][q] = 0.f; acc3[mi][ni][q] = 0.f; }

    // prologue: stages 0..2
    G1_ISSUE(0, 0); CPCOMMIT();
    G1_ISSUE(1, 1); CPCOMMIT();
    G1_ISSUE(2, 2); CPCOMMIT();

    const int KT = DDIM / 32;    // 32, multiple of 4
    for (int kt0 = 0; kt0 < KT; kt0 += 4) {
#pragma unroll
        for (int c = 0; c < 4; c++) {
            const int kt = kt0 + c;
            CPWAIT2();
            __syncthreads();
            const int pf = kt + NST - 1;
            if (pf < KT) G1_ISSUE((c + 3) & 3, pf);
            CPCOMMIT();

            const uint32_t Ab = smb + c * STG1;     // constant stage offset
            const uint32_t Bb = Ab + A1STG;
#pragma unroll
            for (int kc = 0; kc < 2; kc++) {
                unsigned af[2][4];
#pragma unroll
                for (int mi = 0; mi < 2; mi++)
                    ldsm4(af[mi], Ab + (mb + mi * 16) * 80 + afl + kc * 32);
                unsigned b1f[2][4], b3f[2][4];
#pragma unroll
                for (int p = 0; p < 2; p++) {
                    ldsm4(b1f[p], Bb + (nb + p * 16) * 80 + afl + kc * 32);
                    ldsm4(b3f[p], Bb + (64 + nb + p * 16) * 80 + afl + kc * 32);
                }
#pragma unroll
                for (int mi = 0; mi < 2; mi++)
#pragma unroll
                    for (int ni = 0; ni < 4; ni++) {
                        const int p = ni >> 1, s = ni & 1;
                        unsigned bb1[2] = { b1f[p][s], b1f[p][s + 2] };
                        unsigned bb3[2] = { b3f[p][s], b3f[p][s + 2] };
                        mma_fp16(acc1[mi][ni], af[mi], bb1);
                        mma_fp16(acc3[mi][ni], af[mi], bb3);
                    }
            }
        }
    }
#undef G1_ISSUE

    // epilogue: u = silu(h1)*h3 as fp16x2
#pragma unroll
    for (int mi = 0; mi < 2; mi++) {
#pragma unroll
        for (int half = 0; half < 2; half++) {
            int ml = m0 + mb + mi * 16 + gid + half * 8;
            if (ml < Me) {
                int gi = off + ml;
                unsigned* up = g_U + (size_t)gi * (HDIM / 2);
#pragma unroll
                for (int ni = 0; ni < 4; ni++) {
                    int n = n0 + nb + ni * 8 + tig * 2;
                    float vx = silu(acc1[mi][ni][half * 2 + 0]) * acc3[mi][ni][half * 2 + 0];
                    float vy = silu(acc1[mi][ni][half * 2 + 1]) * acc3[mi][ni][half * 2 + 1];
                    up[n >> 1] = f2h2(vx, vy);
                }
            }
        }
    }
}

// ---------------- GEMM2: out[token] += w * (U @ W2^T)  (v2 RED accumulate) ---
// 128m x 128n tile, BK=32, 256 threads (8 warps of 64m x 32n), 4-stage cp.async,
// 2 CTAs/SM (compile-time stage indices keep regs ~120 <= 128 cap).
#define A2STG  (128 * 80)
#define B2STG  (128 * 80)
#define STG2   (A2STG + B2STG)
#define SMEM2_BYTES (NST * STG2)     // 81920 -> 2 CTAs/SM

__global__ __launch_bounds__(256, 2) void gemm2(float* __restrict__ out) {
    const int tileIdx = blockIdx.y;
    if (tileIdx >= g_ntiles) return;
    const int e   = g_tile_e[tileIdx];
    const int m0  = g_tile_m[tileIdx];
    const int off = g_off[e];
    const int Me  = g_off[e + 1] - off;
    const int n0  = blockIdx.x * 128;
    const size_t wst = (size_t)DDIM * HDIM / 2;

    extern __shared__ unsigned char smem[];
    const uint32_t smb = smem_u32(smem);
    const int tid = threadIdx.x;
    const int wid = tid >> 5, lane = tid & 31;

    const char* gsrc[4];
    uint32_t    sdst[4];
#pragma unroll
    for (int j = 0; j < 4; j++) {
        int id = tid + j * 256;
        if (id < 512) {
            int row = id >> 2, kc = id & 3;
            int ml = m0 + row;
            int gi = off + (ml < Me ? ml : 0);
            gsrc[j] = (const char*)g_U + ((size_t)gi * HDIM + kc * 8) * 2;
            sdst[j] = (uint32_t)(row * 80 + kc * 16);
        } else {
            int bid = id - 512;
            int row = bid >> 2, kc = bid & 3;
            gsrc[j] = (const char*)(g_W2h + (size_t)e * wst
                                    + (size_t)(n0 + row) * (HDIM / 2)) + kc * 16;
            sdst[j] = (uint32_t)(A2STG + row * 80 + kc * 16);
        }
    }

#define G2_ISSUE(S, pf) do {                                                \
        uint32_t _b = smb + (S) * STG2;                                     \
        size_t _go = (size_t)(pf) * 64;                                     \
        _Pragma("unroll")                                                   \
        for (int j = 0; j < 4; j++) CPA16(_b + sdst[j], gsrc[j] + _go);     \
    } while (0)

    const int mb = (wid & 1) * 64, nb = (wid >> 1) * 32;
    const uint32_t afl = (lane & 15) * 80 + (lane >> 4) * 16;
    const int gid = lane >> 2, tig = lane & 3;

    float acc[4][4][4];
#pragma unroll
    for (int mi = 0; mi < 4; mi++)
#pragma unroll
        for (int ni = 0; ni < 4; ni++)
#pragma unroll
            for (int q = 0; q < 4; q++) acc[mi][ni][q] = 0.f;

    G2_ISSUE(0, 0); CPCOMMIT();
    G2_ISSUE(1, 1); CPCOMMIT();
    G2_ISSUE(2, 2); CPCOMMIT();

    const int KT = HDIM / 32;    // 64, multiple of 4
    for (int kt0 = 0; kt0 < KT; kt0 += 4) {
#pragma unroll
        for (int c = 0; c < 4; c++) {
            const int kt = kt0 + c;
            CPWAIT2();
            __syncthreads();
            const int pf = kt + NST - 1;
            if (pf < KT) G2_ISSUE((c + 3) & 3, pf);
            CPCOMMIT();

            const uint32_t Ab = smb + c * STG2;
            const uint32_t Bb = Ab + A2STG;
#pragma unroll
            for (int kc = 0; kc < 2; kc++) {
                unsigned af[4][4];
#pragma unroll
                for (int mi = 0; mi < 4; mi++)
                    ldsm4(af[mi], Ab + (mb + mi * 16) * 80 + afl + kc * 32);
                unsigned bf[2][4];
#pragma unroll
                for (int p = 0; p < 2; p++)
                    ldsm4(bf[p], Bb + (nb + p * 16) * 80 + afl + kc * 32);
#pragma unroll
                for (int mi = 0; mi < 4; mi++)
#pragma unroll
                    for (int ni = 0; ni < 4; ni++) {
                        const int p = ni >> 1, s = ni & 1;
                        unsigned bb[2] = { bf[p][s], bf[p][s + 2] };
                        mma_fp16(acc[mi][ni], af[mi], bb);
                    }
            }
        }
    }
#undef G2_ISSUE

    // epilogue: scale + vector-RED accumulate into output token rows
#pragma unroll
    for (int mi = 0; mi < 4; mi++) {
#pragma unroll
        for (int half = 0; half < 2; half++) {
            int ml = m0 + mb + mi * 16 + gid + half * 8;
            if (ml < Me) {
                int gi = off + ml;
                int info = g_rows[gi];
                int tok  = info >> 2;
                int slot = tok * 3 + (info & 3);
                float w = g_wslot[slot];
                float* yp = out + (size_t)tok * DDIM;
#pragma unroll
                for (int ni = 0; ni < 4; ni++) {
                    int n = n0 + nb + ni * 8 + tig * 2;
                    red_v2(yp + n, acc[mi][ni][half * 2 + 0] * w,
                                   acc[mi][ni][half * 2 + 1] * w);
                }
            }
        }
    }
}

// ---------------- launch -----------------------------------------------------
extern "C" void kernel_launch(void* const* d_in, const int* in_sizes, int n_in,
                              void* d_out, int out_size)
{
    const float* h   = (const float*)d_in[0];
    const float* sw1 = (const float*)d_in[1];
    const float* sw2 = (const float*)d_in[2];
    const float* sw3 = (const float*)d_in[3];
    const float* W1  = (const float*)d_in[4];
    const float* W2  = (const float*)d_in[5];
    const float* W3  = (const float*)d_in[6];
    const float* Wg  = (const float*)d_in[7];
    float* out = (float*)d_out;

    static bool attr_done = false;
    if (!attr_done) {
        cudaFuncSetAttribute(gemm1_fused, cudaFuncAttributeMaxDynamicSharedMemorySize, SMEM1_BYTES);
        cudaFuncSetAttribute(gemm2,       cudaFuncAttributeMaxDynamicSharedMemorySize, SMEM2_BYTES);
        attr_done = true;
    }

    zero_kernel<<<1, 32>>>();
    prep_kernel<<<PREP_BLOCKS, PREP_THREADS>>>(
        (const float4*)W1, (const float4*)sw1,
        (const float4*)W3, (const float4*)sw3,
        (const float4*)W2, (const float4*)sw2,
        h, Wg, (float4*)out);
    setup_scatter_kernel<<<1, 1024>>>();

    dim3 grid1(HDIM / 64, MAXTILES);     // 32 n-tiles of 64 h-cols
    gemm1_fused<<<grid1, 256, SMEM1_BYTES>>>();

    dim3 grid2(DDIM / 128, MAXTILES);
    gemm2<<<grid2, 256, SMEM2_BYTES>>>(out);
}